// round 3
// baseline (speedup 1.0000x reference)
#include <cuda_runtime.h>

#define B_    2
#define QLEN  900
#define DIMV  256
#define NH    8
#define HD    32
#define KVLEN 4096
#define GRD   64
#define RPEH  512

// ---------------- scratch (static device globals; no allocation) ----------------
__device__ float d_Kp[B_*NH*KVLEN*HD];   // (b,head,kv,32)
__device__ float d_Vp[B_*NH*KVLEN*HD];   // (b,head,kv,32)
__device__ float d_Qp[B_*NH*QLEN*HD];    // (b,head,q,32), pre-scaled by 1/sqrt(32)
__device__ float d_rpex[B_*NH*QLEN*GRD]; // (b,head,q,w)
__device__ float d_rpey[B_*NH*QLEN*GRD]; // (b,head,q,h)
__device__ float d_ctx[B_*QLEN*DIMV];    // (b,q,256)

// ---------------- tiled fp32 GEMM: C = A(Mx256) @ W(256x256)^T + bias ----------------
// permuted epilogue writes (b,head,row,32) layout for Q/K/V projections.
__global__ void gemm256(const float* __restrict__ A, const float* __restrict__ W,
                        const float* __restrict__ bias, float* __restrict__ C,
                        int M, int rowsPerBatch, float scale, int permuted)
{
    __shared__ float As[16][64];
    __shared__ float Ws[16][64];
    const int bm = blockIdx.x * 64;
    const int bn = blockIdx.y * 64;
    const int tid = threadIdx.x;
    const int tm = (tid >> 4) * 4;
    const int tn = (tid & 15) * 4;
    float acc[4][4];
#pragma unroll
    for (int i = 0; i < 4; i++)
#pragma unroll
        for (int j = 0; j < 4; j++) acc[i][j] = 0.f;

    const int lr = tid >> 2;        // 0..63
    const int lc = (tid & 3) * 4;   // 0,4,8,12

    for (int k0 = 0; k0 < 256; k0 += 16) {
        float4 a4 = make_float4(0.f, 0.f, 0.f, 0.f);
        if (bm + lr < M) a4 = *(const float4*)&A[(bm + lr) * 256 + k0 + lc];
        As[lc + 0][lr] = a4.x; As[lc + 1][lr] = a4.y;
        As[lc + 2][lr] = a4.z; As[lc + 3][lr] = a4.w;
        float4 w4 = *(const float4*)&W[(bn + lr) * 256 + k0 + lc];
        Ws[lc + 0][lr] = w4.x; Ws[lc + 1][lr] = w4.y;
        Ws[lc + 2][lr] = w4.z; Ws[lc + 3][lr] = w4.w;
        __syncthreads();
#pragma unroll
        for (int k = 0; k < 16; k++) {
            float4 av = *(const float4*)&As[k][tm];
            float4 wv = *(const float4*)&Ws[k][tn];
            float a[4] = {av.x, av.y, av.z, av.w};
            float w[4] = {wv.x, wv.y, wv.z, wv.w};
#pragma unroll
            for (int i = 0; i < 4; i++)
#pragma unroll
                for (int j = 0; j < 4; j++) acc[i][j] += a[i] * w[j];
        }
        __syncthreads();
    }

#pragma unroll
    for (int i = 0; i < 4; i++) {
        int row = bm + tm + i;
        if (row >= M) continue;
#pragma unroll
        for (int j = 0; j < 4; j++) {
            int col = bn + tn + j;
            float v = (acc[i][j] + bias[col]) * scale;
            if (permuted) {
                int b = row / rowsPerBatch;
                int r = row - b * rowsPerBatch;
                int head = col >> 5;
                int d = col & 31;
                C[((b * NH + head) * rowsPerBatch + r) * HD + d] = v;
            } else {
                C[row * 256 + col] = v;
            }
        }
    }
}

// ---------------- RPE MLP: per (b,q,axis) block ----------------
// hidden[j] = relu(w1[j][0]*d0 + w1[j][1]*d1 + b1[j]); out[head,p] = sum_j hidden*w2[head][j]
__global__ void rpe_kernel(const float* __restrict__ refpts,
                           const float* __restrict__ w1, const float* __restrict__ b1,
                           const float* __restrict__ w2, float* __restrict__ out, int axis)
{
    __shared__ float2 w1s[RPEH];
    __shared__ float  b1s[RPEH];
    __shared__ float  w2s[RPEH * NH]; // [j][head]

    const int q = blockIdx.x;
    const int b = blockIdx.y;
    const int tid = threadIdx.x;

    for (int i = tid; i < RPEH; i += 256) {
        w1s[i] = make_float2(w1[i * 2], w1[i * 2 + 1]);
        b1s[i] = b1[i];
    }
    for (int i = tid; i < RPEH * NH; i += 256) {
        int j = i >> 3, h = i & 7;
        w2s[i] = w2[h * RPEH + j];
    }

    const float* rp = refpts + (b * QLEN + q) * 4;
    const float c = rp[axis];
    const float s = rp[2 + axis];
    const float lo = (c - 0.5f * s) * 1024.0f;  // grid(64) * stride(16)
    const float hi = (c + 0.5f * s) * 1024.0f;
    __syncthreads();

    const int p  = tid >> 2;   // position 0..63
    const int qr = tid & 3;    // quarter of hidden dim
    const float px = (p + 0.5f) * 16.0f;
    const float d0 = lo - px;
    const float d1 = hi - px;

    float h8[8];
#pragma unroll
    for (int h = 0; h < 8; h++) h8[h] = 0.f;

#pragma unroll 4
    for (int i = 0; i < 128; i++) {
        int j = qr + i * 4;     // interleaved -> conflict-light
        float2 w = w1s[j];
        float hv = fmaxf(w.x * d0 + w.y * d1 + b1s[j], 0.0f);
        const float4* wr = (const float4*)&w2s[j * 8];
        float4 wa = wr[0], wb = wr[1];
        h8[0] += hv * wa.x; h8[1] += hv * wa.y; h8[2] += hv * wa.z; h8[3] += hv * wa.w;
        h8[4] += hv * wb.x; h8[5] += hv * wb.y; h8[6] += hv * wb.z; h8[7] += hv * wb.w;
    }
#pragma unroll
    for (int m = 1; m <= 2; m <<= 1)
#pragma unroll
        for (int h = 0; h < 8; h++) h8[h] += __shfl_xor_sync(0xffffffffu, h8[h], m);

    if (qr == 0) {
#pragma unroll
        for (int h = 0; h < 8; h++)
            out[((b * NH + h) * QLEN + q) * GRD + p] = h8[h];
    }
}

// ---------------- fused attention with online softmax + decomposed RPE ----------------
// block: 256 threads, 32 queries for one (b,head). KV tile = 64 = one grid row.
__global__ void attn_kernel(const int* __restrict__ mask)
{
    __shared__ float Qs[32][HD];       // 4 KB
    __shared__ float rxs[32][GRD];     // 8 KB
    __shared__ float rys[32][GRD];     // 8 KB
    __shared__ float Ks[64][36];       // 9.2 KB (pad 36 -> conflict-free f4 rows)
    __shared__ float Vs[64][36];       // 9.2 KB
    __shared__ float Ps[32][65];       // 8.3 KB (pad 65)
    __shared__ float msks[64];

    const int bh = blockIdx.y;         // b*8 + head
    const int b  = bh >> 3;
    const int head = bh & 7;
    const int q0 = blockIdx.x * 32;
    const int tid = threadIdx.x;

    // load Q tile (pre-scaled)
    {
        int r = tid >> 3, c = (tid & 7) * 4;
        int q = q0 + r;
        float4 v = make_float4(0.f, 0.f, 0.f, 0.f);
        if (q < QLEN) v = *(const float4*)&d_Qp[(bh * QLEN + q) * HD + c];
        *(float4*)&Qs[r][c] = v;
    }
    // load rpe_x / rpe_y rows for this head
    {
        int r = tid >> 3, c = (tid & 7) * 8;
        int q = q0 + r;
        float4 z = make_float4(0.f, 0.f, 0.f, 0.f);
        if (q < QLEN) {
            const float* px = d_rpex + (bh * QLEN + q) * GRD + c;
            const float* py = d_rpey + (bh * QLEN + q) * GRD + c;
            *(float4*)&rxs[r][c]     = *(const float4*)px;
            *(float4*)&rxs[r][c + 4] = *(const float4*)(px + 4);
            *(float4*)&rys[r][c]     = *(const float4*)py;
            *(float4*)&rys[r][c + 4] = *(const float4*)(py + 4);
        } else {
            *(float4*)&rxs[r][c] = z; *(float4*)&rxs[r][c + 4] = z;
            *(float4*)&rys[r][c] = z; *(float4*)&rys[r][c + 4] = z;
        }
    }
    __syncthreads();

    const int myq = tid >> 3;   // query within tile
    const int g   = tid & 7;    // kv-group / d-group
    float qreg[32];
#pragma unroll
    for (int c = 0; c < 8; c++) {
        float4 v = *(const float4*)&Qs[myq][c * 4];
        qreg[c * 4 + 0] = v.x; qreg[c * 4 + 1] = v.y;
        qreg[c * 4 + 2] = v.z; qreg[c * 4 + 3] = v.w;
    }

    float m_run = -1e30f, l_run = 0.0f;
    float4 acc = make_float4(0.f, 0.f, 0.f, 0.f);

    const float* Kbase = d_Kp + (size_t)bh * KVLEN * HD;
    const float* Vbase = d_Vp + (size_t)bh * KVLEN * HD;
    const int*   mbase = mask + b * KVLEN;

    for (int t = 0; t < 64; t++) {
        // stage K/V tile + mask
        {
            int r = tid >> 2, c = (tid & 3) * 8;
            const float4* kp = (const float4*)&Kbase[(t * 64 + r) * HD + c];
            const float4* vp = (const float4*)&Vbase[(t * 64 + r) * HD + c];
            *(float4*)&Ks[r][c]     = kp[0];
            *(float4*)&Ks[r][c + 4] = kp[1];
            *(float4*)&Vs[r][c]     = vp[0];
            *(float4*)&Vs[r][c + 4] = vp[1];
            if (tid < 64) msks[tid] = -100.0f * (float)mbase[t * 64 + tid];
        }
        __syncthreads();

        // QK^T for 8 kv per thread, + rpe + mask
        float sc[8];
        const float ry = rys[myq][t];   // kv tile == grid row t
#pragma unroll
        for (int i = 0; i < 8; i++) {
            int kv = g + 8 * i;
            float s = 0.f;
#pragma unroll
            for (int c = 0; c < 8; c++) {
                float4 k4 = *(const float4*)&Ks[kv][c * 4];
                s += qreg[c * 4 + 0] * k4.x + qreg[c * 4 + 1] * k4.y
                   + qreg[c * 4 + 2] * k4.z + qreg[c * 4 + 3] * k4.w;
            }
            sc[i] = s + rxs[myq][kv] + ry + msks[kv];
        }

        // online softmax (8-thread group per query)
        float mloc = sc[0];
#pragma unroll
        for (int i = 1; i < 8; i++) mloc = fmaxf(mloc, sc[i]);
        mloc = fmaxf(mloc, __shfl_xor_sync(0xffffffffu, mloc, 1));
        mloc = fmaxf(mloc, __shfl_xor_sync(0xffffffffu, mloc, 2));
        mloc = fmaxf(mloc, __shfl_xor_sync(0xffffffffu, mloc, 4));
        float m_new = fmaxf(m_run, mloc);
        float fac = __expf(m_run - m_new);
        float psum = 0.f;
#pragma unroll
        for (int i = 0; i < 8; i++) {
            float p = __expf(sc[i] - m_new);
            Ps[myq][g + 8 * i] = p;
            psum += p;
        }
        psum += __shfl_xor_sync(0xffffffffu, psum, 1);
        psum += __shfl_xor_sync(0xffffffffu, psum, 2);
        psum += __shfl_xor_sync(0xffffffffu, psum, 4);
        l_run = l_run * fac + psum;
        m_run = m_new;
        acc.x *= fac; acc.y *= fac; acc.z *= fac; acc.w *= fac;
        __syncthreads();

        // P @ V   (thread owns (myq, d = g*4..g*4+3))
#pragma unroll 16
        for (int kv = 0; kv < 64; kv++) {
            float p = Ps[myq][kv];
            float4 v4 = *(const float4*)&Vs[kv][g * 4];
            acc.x += p * v4.x; acc.y += p * v4.y;
            acc.z += p * v4.z; acc.w += p * v4.w;
        }
        __syncthreads();
    }

    int q = q0 + myq;
    if (q < QLEN) {
        float inv = 1.0f / l_run;
        float4 o = make_float4(acc.x * inv, acc.y * inv, acc.z * inv, acc.w * inv);
        *(float4*)&d_ctx[(b * QLEN + q) * DIMV + head * HD + g * 4] = o;
    }
}

// ---------------- launch ----------------
extern "C" void kernel_launch(void* const* d_in, const int* in_sizes, int n_in,
                              void* d_out, int out_size)
{
    const float* hidden = (const float*)d_in[0];
    const float* refpts = (const float*)d_in[1];
    const float* kvst   = (const float*)d_in[2];
    // d_in[3] spatial_shapes (int64) -> constants hardcoded (64,64)
    const int*   amask  = (const int*)d_in[4];
    const float* m1w1 = (const float*)d_in[5];
    const float* m1b1 = (const float*)d_in[6];
    const float* m1w2 = (const float*)d_in[7];
    const float* m2w1 = (const float*)d_in[8];
    const float* m2b1 = (const float*)d_in[9];
    const float* m2w2 = (const float*)d_in[10];
    const float* qw = (const float*)d_in[11];
    const float* qb = (const float*)d_in[12];
    const float* kw = (const float*)d_in[13];
    const float* kb = (const float*)d_in[14];
    const float* vw = (const float*)d_in[15];
    const float* vb = (const float*)d_in[16];
    const float* ow = (const float*)d_in[17];
    const float* ob = (const float*)d_in[18];
    float* out = (float*)d_out;

    float *pK, *pV, *pQ, *pRX, *pRY, *pCTX;
    cudaGetSymbolAddress((void**)&pK,   d_Kp);
    cudaGetSymbolAddress((void**)&pV,   d_Vp);
    cudaGetSymbolAddress((void**)&pQ,   d_Qp);
    cudaGetSymbolAddress((void**)&pRX,  d_rpex);
    cudaGetSymbolAddress((void**)&pRY,  d_rpey);
    cudaGetSymbolAddress((void**)&pCTX, d_ctx);

    dim3 blk(256);
    const float qscale = 0.17677669529663687f;  // 1/sqrt(32)

    gemm256<<<dim3(128, 4), blk>>>(kvst,   kw, kb, pK,   B_ * KVLEN, KVLEN, 1.0f,   1);
    gemm256<<<dim3(128, 4), blk>>>(kvst,   vw, vb, pV,   B_ * KVLEN, KVLEN, 1.0f,   1);
    gemm256<<<dim3(29, 4),  blk>>>(hidden, qw, qb, pQ,   B_ * QLEN,  QLEN,  qscale, 1);
    rpe_kernel<<<dim3(QLEN, B_), blk>>>(refpts, m1w1, m1b1, m1w2, pRX, 0);
    rpe_kernel<<<dim3(QLEN, B_), blk>>>(refpts, m2w1, m2b1, m2w2, pRY, 1);
    attn_kernel<<<dim3(29, B_ * NH), blk>>>(amask);
    gemm256<<<dim3(29, 4),  blk>>>(pCTX,   ow, ob, out,  B_ * QLEN,  QLEN,  1.0f,   0);
}

// round 5
// speedup vs baseline: 3.3872x; 3.3872x over previous
#include <cuda_runtime.h>
#include <cuda_fp16.h>
#include <cstdint>

#define B_    2
#define QLEN  900
#define DIMV  256
#define NH    8
#define HD    32
#define KVLEN 4096
#define GRD   64
#define RPEH  512

// ---------------- scratch ----------------
__device__ __half d_Qh[B_*NH*QLEN*HD];    // (b,h,q,32) f16 pre-scaled
__device__ __half d_Kh[B_*NH*KVLEN*HD];   // (b,h,kv,32) f16
__device__ __half d_Vh[B_*NH*KVLEN*HD];   // (b,h,kv,32) f16
__device__ float  d_rpex[B_*NH*QLEN*GRD];
__device__ float  d_rpey[B_*NH*QLEN*GRD];
__device__ float  d_ctx[B_*QLEN*DIMV];

// ---------------- mma/ldmatrix helpers (sm_80-class PTX, compiles at compute_100) ----
__device__ __forceinline__ void ldmx4(uint32_t* r, uint32_t a) {
    asm volatile("ldmatrix.sync.aligned.m8n8.x4.shared.b16 {%0,%1,%2,%3}, [%4];"
                 : "=r"(r[0]), "=r"(r[1]), "=r"(r[2]), "=r"(r[3]) : "r"(a));
}
__device__ __forceinline__ void ldmx2(uint32_t* r, uint32_t a) {
    asm volatile("ldmatrix.sync.aligned.m8n8.x2.shared.b16 {%0,%1}, [%2];"
                 : "=r"(r[0]), "=r"(r[1]) : "r"(a));
}
__device__ __forceinline__ void ldmx2t(uint32_t* r, uint32_t a) {
    asm volatile("ldmatrix.sync.aligned.m8n8.x2.trans.shared.b16 {%0,%1}, [%2];"
                 : "=r"(r[0]), "=r"(r[1]) : "r"(a));
}
__device__ __forceinline__ void mma16816(float* c, const uint32_t* a, const uint32_t* b) {
    asm volatile("mma.sync.aligned.m16n8k16.row.col.f32.f16.f16.f32 "
                 "{%0,%1,%2,%3}, {%4,%5,%6,%7}, {%8,%9}, {%0,%1,%2,%3};"
                 : "+f"(c[0]), "+f"(c[1]), "+f"(c[2]), "+f"(c[3])
                 : "r"(a[0]), "r"(a[1]), "r"(a[2]), "r"(a[3]), "r"(b[0]), "r"(b[1]));
}
__device__ __forceinline__ uint32_t smem_u32(const void* p) {
    return (uint32_t)__cvta_generic_to_shared(p);
}
__device__ __forceinline__ uint32_t packh2(float a, float b) {
    __half2 h = __floats2half2_rn(a, b);
    return *(uint32_t*)&h;
}

// ---------------- fp32 GEMM: C = A(Mx256) @ W(256x256)^T + bias ----------------
// mode 0: float C[row*256+col]; mode 1: half (b,head,row,32)
__global__ void gemm256(const float* __restrict__ A, const float* __restrict__ W,
                        const float* __restrict__ bias, void* __restrict__ Cv,
                        int M, int rowsPerBatch, float scale, int mode)
{
    __shared__ float As[16][64];
    __shared__ float Ws[16][64];
    const int bm = blockIdx.x * 64;
    const int bn = blockIdx.y * 64;
    const int tid = threadIdx.x;
    const int tm = (tid >> 4) * 4;
    const int tn = (tid & 15) * 4;
    float acc[4][4];
#pragma unroll
    for (int i = 0; i < 4; i++)
#pragma unroll
        for (int j = 0; j < 4; j++) acc[i][j] = 0.f;

    const int lr = tid >> 2;
    const int lc = (tid & 3) * 4;

    for (int k0 = 0; k0 < 256; k0 += 16) {
        float4 a4 = make_float4(0.f, 0.f, 0.f, 0.f);
        if (bm + lr < M) a4 = *(const float4*)&A[(bm + lr) * 256 + k0 + lc];
        As[lc + 0][lr] = a4.x; As[lc + 1][lr] = a4.y;
        As[lc + 2][lr] = a4.z; As[lc + 3][lr] = a4.w;
        float4 w4 = *(const float4*)&W[(bn + lr) * 256 + k0 + lc];
        Ws[lc + 0][lr] = w4.x; Ws[lc + 1][lr] = w4.y;
        Ws[lc + 2][lr] = w4.z; Ws[lc + 3][lr] = w4.w;
        __syncthreads();
#pragma unroll
        for (int k = 0; k < 16; k++) {
            float4 av = *(const float4*)&As[k][tm];
            float4 wv = *(const float4*)&Ws[k][tn];
            float a[4] = {av.x, av.y, av.z, av.w};
            float w[4] = {wv.x, wv.y, wv.z, wv.w};
#pragma unroll
            for (int i = 0; i < 4; i++)
#pragma unroll
                for (int j = 0; j < 4; j++) acc[i][j] += a[i] * w[j];
        }
        __syncthreads();
    }

    float vv[4][4];
#pragma unroll
    for (int i = 0; i < 4; i++)
#pragma unroll
        for (int j = 0; j < 4; j++) vv[i][j] = (acc[i][j] + bias[bn + tn + j]) * scale;

    if (mode == 0) {
        float* C = (float*)Cv;
#pragma unroll
        for (int i = 0; i < 4; i++) {
            int row = bm + tm + i;
            if (row < M) *(float4*)&C[row * 256 + bn + tn] = *(float4*)vv[i];
        }
    } else {
        __half* C = (__half*)Cv;
        int head = (bn + tn) >> 5, d = (bn + tn) & 31;
#pragma unroll
        for (int i = 0; i < 4; i++) {
            int row = bm + tm + i;
            if (row >= M) continue;
            int b = row / rowsPerBatch, r = row - b * rowsPerBatch;
            uint2 u;
            u.x = packh2(vv[i][0], vv[i][1]);
            u.y = packh2(vv[i][2], vv[i][3]);
            *(uint2*)&C[((size_t)((b * NH + head) * rowsPerBatch + r)) * HD + d] = u;
        }
    }
}

// ---------------- RPE MLP: 2 queries per block ----------------
__global__ void rpe_kernel2(const float* __restrict__ refpts,
                            const float* __restrict__ w1, const float* __restrict__ b1,
                            const float* __restrict__ w2, float* __restrict__ out, int axis)
{
    __shared__ float2 w1s[RPEH];
    __shared__ float  b1s[RPEH];
    __shared__ float  w2s[RPEH * NH];

    const int q0 = blockIdx.x * 2;
    const int b = blockIdx.y;
    const int tid = threadIdx.x;

    for (int i = tid; i < RPEH; i += 256) {
        w1s[i] = make_float2(w1[i * 2], w1[i * 2 + 1]);
        b1s[i] = b1[i];
    }
    for (int i = tid; i < RPEH * NH; i += 256) {
        int j = i >> 3, h = i & 7;
        w2s[i] = w2[h * RPEH + j];
    }

    const float* rpA = refpts + ((size_t)b * QLEN + q0) * 4;
    const float cA = rpA[axis],     sA = rpA[2 + axis];
    const float cB = rpA[4 + axis], sB = rpA[6 + axis];
    const float loA = (cA - 0.5f * sA) * 1024.0f, hiA = (cA + 0.5f * sA) * 1024.0f;
    const float loB = (cB - 0.5f * sB) * 1024.0f, hiB = (cB + 0.5f * sB) * 1024.0f;
    __syncthreads();

    const int p  = tid >> 2;
    const int qr = tid & 3;
    const float px = (p + 0.5f) * 16.0f;
    const float d0A = loA - px, d1A = hiA - px;
    const float d0B = loB - px, d1B = hiB - px;

    float hA[8], hB[8];
#pragma unroll
    for (int h = 0; h < 8; h++) { hA[h] = 0.f; hB[h] = 0.f; }

#pragma unroll 4
    for (int i = 0; i < 128; i++) {
        int j = qr + i * 4;
        float2 w = w1s[j];
        float bb = b1s[j];
        float hvA = fmaxf(w.x * d0A + w.y * d1A + bb, 0.0f);
        float hvB = fmaxf(w.x * d0B + w.y * d1B + bb, 0.0f);
        const float4* wr = (const float4*)&w2s[j * 8];
        float4 wa = wr[0], wb = wr[1];
        hA[0] += hvA * wa.x; hA[1] += hvA * wa.y; hA[2] += hvA * wa.z; hA[3] += hvA * wa.w;
        hA[4] += hvA * wb.x; hA[5] += hvA * wb.y; hA[6] += hvA * wb.z; hA[7] += hvA * wb.w;
        hB[0] += hvB * wa.x; hB[1] += hvB * wa.y; hB[2] += hvB * wa.z; hB[3] += hvB * wa.w;
        hB[4] += hvB * wb.x; hB[5] += hvB * wb.y; hB[6] += hvB * wb.z; hB[7] += hvB * wb.w;
    }
#pragma unroll
    for (int m = 1; m <= 2; m <<= 1)
#pragma unroll
        for (int h = 0; h < 8; h++) {
            hA[h] += __shfl_xor_sync(0xffffffffu, hA[h], m);
            hB[h] += __shfl_xor_sync(0xffffffffu, hB[h], m);
        }

    if (qr == 0) {
#pragma unroll
        for (int h = 0; h < 8; h++) {
            out[((size_t)(b * NH + h) * QLEN + q0) * GRD + p]     = hA[h];
            out[((size_t)(b * NH + h) * QLEN + q0 + 1) * GRD + p] = hB[h];
        }
    }
}

// ---------------- HMMA flash attention ----------------
// CTA = one (b,head) x 64 queries; 4 warps x m16; kv tiles of 64.
#define PK 40        // K/V/Q smem pitch in halves (80B rows -> conflict-free ldmatrix)
#define PR 68        // rpe smem pitch in floats
#define QS_OFF  0
#define KS_OFF  5120
#define VS_OFF  10240
#define RX_OFF  15360
#define RY_OFF  32768
#define MK_OFF  50176
#define ATTN_SMEM 66560

__global__ void __launch_bounds__(128) attn_mma(const int* __restrict__ mask)
{
    extern __shared__ char smem[];
    __half* Qs  = (__half*)(smem + QS_OFF);
    __half* Ks  = (__half*)(smem + KS_OFF);
    __half* Vs  = (__half*)(smem + VS_OFF);
    float*  rxs = (float*)(smem + RX_OFF);
    float*  rys = (float*)(smem + RY_OFF);
    float*  mks = (float*)(smem + MK_OFF);

    const int tid = threadIdx.x;
    const int lane = tid & 31;
    const int wid = tid >> 5;
    const int bh = blockIdx.y;
    const int b = bh >> 3;
    const int head = bh & 7;
    const int q0 = blockIdx.x * 64;

    // mask -> float
    const int* mb = mask + b * KVLEN;
    for (int i = tid; i < KVLEN; i += 128) mks[i] = -100.0f * (float)mb[i];

    // Q tile -> smem (64 rows x 32 halves, pitch 40)
    {
        int row = tid >> 1, seg = tid & 1;
        int q = q0 + row;
        uint4 v0 = make_uint4(0, 0, 0, 0), v1 = make_uint4(0, 0, 0, 0);
        if (q < QLEN) {
            const uint4* qp = (const uint4*)(d_Qh + ((size_t)bh * QLEN + q) * HD + seg * 16);
            v0 = qp[0]; v1 = qp[1];
        }
        *(uint4*)(Qs + row * PK + seg * 16)     = v0;
        *(uint4*)(Qs + row * PK + seg * 16 + 8) = v1;
    }
    // rx/ry tiles (64 rows x 64 floats, pitch 68)
    {
        int row = tid >> 1, sb = (tid & 1) * 32;
        int q = q0 + row;
        if (q < QLEN) {
            const float4* px = (const float4*)(d_rpex + ((size_t)bh * QLEN + q) * GRD + sb);
            const float4* py = (const float4*)(d_rpey + ((size_t)bh * QLEN + q) * GRD + sb);
#pragma unroll
            for (int u = 0; u < 8; u++) {
                *(float4*)(rxs + row * PR + sb + u * 4) = px[u];
                *(float4*)(rys + row * PR + sb + u * 4) = py[u];
            }
        } else {
            float4 z = make_float4(0.f, 0.f, 0.f, 0.f);
#pragma unroll
            for (int u = 0; u < 8; u++) {
                *(float4*)(rxs + row * PR + sb + u * 4) = z;
                *(float4*)(rys + row * PR + sb + u * 4) = z;
            }
        }
    }
    __syncthreads();

    // Q fragments (held for whole kernel)
    uint32_t aQ[2][4];
    {
        uint32_t base = smem_u32(Qs);
        int m = wid * 16 + (lane & 15);
        uint32_t a0 = base + (uint32_t)(m * PK + ((lane >> 4) * 8)) * 2;
        ldmx4(aQ[0], a0);
        ldmx4(aQ[1], a0 + 32);  // +16 halves (d 16..31)
    }

    const uint32_t KsB = smem_u32(Ks);
    const uint32_t VsB = smem_u32(Vs);

    float oc[4][4];
#pragma unroll
    for (int i = 0; i < 4; i++)
#pragma unroll
        for (int j = 0; j < 4; j++) oc[i][j] = 0.f;
    float m_run0 = -1e30f, m_run1 = -1e30f, l_run0 = 0.f, l_run1 = 0.f;

    const __half* Kb = d_Kh + (size_t)bh * KVLEN * HD;
    const __half* Vb = d_Vh + (size_t)bh * KVLEN * HD;

    const int r0 = wid * 16 + (lane >> 2);  // local q row (and r0+8)
    const int cb = 2 * (lane & 3);

    for (int t = 0; t < 64; t++) {
        __syncthreads();
        // K/V tile -> smem
        {
            int row = tid >> 1, seg = tid & 1;
            const uint4* kp = (const uint4*)(Kb + (size_t)(t * 64 + row) * HD + seg * 16);
            const uint4* vp = (const uint4*)(Vb + (size_t)(t * 64 + row) * HD + seg * 16);
            uint4 k0 = kp[0], k1 = kp[1], v0 = vp[0], v1 = vp[1];
            *(uint4*)(Ks + row * PK + seg * 16)     = k0;
            *(uint4*)(Ks + row * PK + seg * 16 + 8) = k1;
            *(uint4*)(Vs + row * PK + seg * 16)     = v0;
            *(uint4*)(Vs + row * PK + seg * 16 + 8) = v1;
        }
        __syncthreads();

        // S = Q @ K^T
        float sc[8][4];
#pragma unroll
        for (int j = 0; j < 8; j++) {
            sc[j][0] = sc[j][1] = sc[j][2] = sc[j][3] = 0.f;
            int rr = j * 8 + (lane & 7);
            uint32_t addr = KsB + (uint32_t)(rr * PK + ((lane >> 3) & 1) * 8) * 2;
            uint32_t bk0[2], bk1[2];
            ldmx2(bk0, addr);        // d 0..15
            ldmx2(bk1, addr + 32);   // d 16..31
            mma16816(sc[j], aQ[0], bk0);
            mma16816(sc[j], aQ[1], bk1);
        }

        // bias + row max
        float ry0 = rys[r0 * PR + t];
        float ry1 = rys[(r0 + 8) * PR + t];
        float mx0 = -1e30f, mx1 = -1e30f;
#pragma unroll
        for (int j = 0; j < 8; j++) {
            int n = j * 8 + cb;
            float2 rxa = *(float2*)(rxs + r0 * PR + n);
            float2 rxb = *(float2*)(rxs + (r0 + 8) * PR + n);
            float2 mk  = *(float2*)(mks + t * 64 + n);
            sc[j][0] += rxa.x + ry0 + mk.x;
            sc[j][1] += rxa.y + ry0 + mk.y;
            sc[j][2] += rxb.x + ry1 + mk.x;
            sc[j][3] += rxb.y + ry1 + mk.y;
            mx0 = fmaxf(mx0, fmaxf(sc[j][0], sc[j][1]));
            mx1 = fmaxf(mx1, fmaxf(sc[j][2], sc[j][3]));
        }
        mx0 = fmaxf(mx0, __shfl_xor_sync(0xffffffffu, mx0, 1));
        mx0 = fmaxf(mx0, __shfl_xor_sync(0xffffffffu, mx0, 2));
        mx1 = fmaxf(mx1, __shfl_xor_sync(0xffffffffu, mx1, 1));
        mx1 = fmaxf(mx1, __shfl_xor_sync(0xffffffffu, mx1, 2));

        float mn0 = fmaxf(m_run0, mx0), mn1 = fmaxf(m_run1, mx1);
        float f0 = __expf(m_run0 - mn0), f1 = __expf(m_run1 - mn1);
        m_run0 = mn0; m_run1 = mn1;

        float la0 = 0.f, la1 = 0.f;
        uint32_t pa[4][4];
#pragma unroll
        for (int j = 0; j < 8; j++) {
            float p0 = __expf(sc[j][0] - mn0);
            float p1 = __expf(sc[j][1] - mn0);
            float p2 = __expf(sc[j][2] - mn1);
            float p3 = __expf(sc[j][3] - mn1);
            la0 += p0 + p1; la1 += p2 + p3;
            int kt = j >> 1, hi = j & 1;
            pa[kt][2 * hi]     = packh2(p0, p1);
            pa[kt][2 * hi + 1] = packh2(p2, p3);
        }
        la0 += __shfl_xor_sync(0xffffffffu, la0, 1);
        la0 += __shfl_xor_sync(0xffffffffu, la0, 2);
        la1 += __shfl_xor_sync(0xffffffffu, la1, 1);
        la1 += __shfl_xor_sync(0xffffffffu, la1, 2);
        l_run0 = l_run0 * f0 + la0;
        l_run1 = l_run1 * f1 + la1;

#pragma unroll
        for (int no = 0; no < 4; no++) {
            oc[no][0] *= f0; oc[no][1] *= f0;
            oc[no][2] *= f1; oc[no][3] *= f1;
        }

        // O += P @ V
#pragma unroll
        for (int kt = 0; kt < 4; kt++) {
            uint32_t addr = VsB + (uint32_t)((kt * 16 + (lane & 15)) * PK) * 2;
#pragma unroll
            for (int no = 0; no < 4; no++) {
                uint32_t bv[2];
                ldmx2t(bv, addr + (uint32_t)(no * 8) * 2);
                mma16816(oc[no], pa[kt], bv);
            }
        }
    }

    // write ctx (fp32)
    {
        float inv0 = 1.0f / l_run0;
        float inv1 = 1.0f / l_run1;
        int qa = q0 + r0, qb = qa + 8;
#pragma unroll
        for (int no = 0; no < 4; no++) {
            int col = head * HD + no * 8 + cb;
            if (qa < QLEN) {
                float2 v = make_float2(oc[no][0] * inv0, oc[no][1] * inv0);
                *(float2*)&d_ctx[((size_t)b * QLEN + qa) * DIMV + col] = v;
            }
            if (qb < QLEN) {
                float2 v = make_float2(oc[no][2] * inv1, oc[no][3] * inv1);
                *(float2*)&d_ctx[((size_t)b * QLEN + qb) * DIMV + col] = v;
            }
        }
    }
}

// ---------------- launch ----------------
extern "C" void kernel_launch(void* const* d_in, const int* in_sizes, int n_in,
                              void* d_out, int out_size)
{
    const float* hidden = (const float*)d_in[0];
    const float* refpts = (const float*)d_in[1];
    const float* kvst   = (const float*)d_in[2];
    const int*   amask  = (const int*)d_in[4];
    const float* m1w1 = (const float*)d_in[5];
    const float* m1b1 = (const float*)d_in[6];
    const float* m1w2 = (const float*)d_in[7];
    const float* m2w1 = (const float*)d_in[8];
    const float* m2b1 = (const float*)d_in[9];
    const float* m2w2 = (const float*)d_in[10];
    const float* qw = (const float*)d_in[11];
    const float* qb = (const float*)d_in[12];
    const float* kw = (const float*)d_in[13];
    const float* kb = (const float*)d_in[14];
    const float* vw = (const float*)d_in[15];
    const float* vb = (const float*)d_in[16];
    const float* ow = (const float*)d_in[17];
    const float* ob = (const float*)d_in[18];
    float* out = (float*)d_out;

    void *pQ, *pK, *pV, *pRX, *pRY, *pCTX;
    cudaGetSymbolAddress(&pQ,  d_Qh);
    cudaGetSymbolAddress(&pK,  d_Kh);
    cudaGetSymbolAddress(&pV,  d_Vh);
    cudaGetSymbolAddress(&pRX, d_rpex);
    cudaGetSymbolAddress(&pRY, d_rpey);
    cudaGetSymbolAddress(&pCTX, d_ctx);

    static int smem_set = 0;
    if (!smem_set) {
        cudaFuncSetAttribute(attn_mma, cudaFuncAttributeMaxDynamicSharedMemorySize, ATTN_SMEM);
        smem_set = 1;
    }

    dim3 blk(256);
    const float qscale = 0.17677669529663687f;  // 1/sqrt(32)

    gemm256<<<dim3(128, 4), blk>>>(kvst,   kw, kb, pK, B_ * KVLEN, KVLEN, 1.0f,   1);
    gemm256<<<dim3(128, 4), blk>>>(kvst,   vw, vb, pV, B_ * KVLEN, KVLEN, 1.0f,   1);
    gemm256<<<dim3(29, 4),  blk>>>(hidden, qw, qb, pQ, B_ * QLEN,  QLEN,  qscale, 1);
    rpe_kernel2<<<dim3(QLEN / 2, B_), blk>>>(refpts, m1w1, m1b1, m1w2, (float*)pRX, 0);
    rpe_kernel2<<<dim3(QLEN / 2, B_), blk>>>(refpts, m2w1, m2b1, m2w2, (float*)pRY, 1);
    attn_mma<<<dim3((QLEN + 63) / 64, B_ * NH), 128, ATTN_SMEM>>>(amask);
    gemm256<<<dim3(29, 4),  blk>>>((const float*)pCTX, ow, ob, out, B_ * QLEN, QLEN, 1.0f, 0);
}

// round 6
// speedup vs baseline: 4.4491x; 1.3135x over previous
#include <cuda_runtime.h>
#include <cuda_fp16.h>
#include <cstdint>

#define B_    2
#define QLEN  900
#define DIMV  256
#define NH    8
#define HD    32
#define KVLEN 4096
#define GRD   64
#define RPEH  512

// ---------------- scratch ----------------
__device__ __half d_Qh[B_*NH*QLEN*HD];    // (b,h,q,32) f16 pre-scaled
__device__ __half d_Kh[B_*NH*KVLEN*HD];   // (b,h,kv,32) f16
__device__ __half d_Vh[B_*NH*KVLEN*HD];   // (b,h,kv,32) f16
__device__ __half d_ctxh[B_*QLEN*DIMV];   // (b,q,256) f16
__device__ float  d_rpex[B_*NH*QLEN*GRD];
__device__ float  d_rpey[B_*NH*QLEN*GRD];

// ---------------- mma/ldmatrix helpers ----------------
__device__ __forceinline__ void ldmx4(uint32_t* r, uint32_t a) {
    asm volatile("ldmatrix.sync.aligned.m8n8.x4.shared.b16 {%0,%1,%2,%3}, [%4];"
                 : "=r"(r[0]), "=r"(r[1]), "=r"(r[2]), "=r"(r[3]) : "r"(a));
}
__device__ __forceinline__ void ldmx2(uint32_t* r, uint32_t a) {
    asm volatile("ldmatrix.sync.aligned.m8n8.x2.shared.b16 {%0,%1}, [%2];"
                 : "=r"(r[0]), "=r"(r[1]) : "r"(a));
}
__device__ __forceinline__ void ldmx2t(uint32_t* r, uint32_t a) {
    asm volatile("ldmatrix.sync.aligned.m8n8.x2.trans.shared.b16 {%0,%1}, [%2];"
                 : "=r"(r[0]), "=r"(r[1]) : "r"(a));
}
__device__ __forceinline__ void mma16816(float* c, const uint32_t* a, const uint32_t* b) {
    asm volatile("mma.sync.aligned.m16n8k16.row.col.f32.f16.f16.f32 "
                 "{%0,%1,%2,%3}, {%4,%5,%6,%7}, {%8,%9}, {%0,%1,%2,%3};"
                 : "+f"(c[0]), "+f"(c[1]), "+f"(c[2]), "+f"(c[3])
                 : "r"(a[0]), "r"(a[1]), "r"(a[2]), "r"(a[3]), "r"(b[0]), "r"(b[1]));
}
__device__ __forceinline__ uint32_t smem_u32(const void* p) {
    return (uint32_t)__cvta_generic_to_shared(p);
}
__device__ __forceinline__ uint32_t packh2(float a, float b) {
    __half2 h = __floats2half2_rn(a, b);
    return *(uint32_t*)&h;
}

// ---------------- HMMA GEMM: C = A(Mx256) @ W(256x256)^T + bias ----------------
// A: fp32 (Af) or f16 (Ah, when Af==nullptr). W fp32, converted to f16 on stage.
// mode 0: float C[row*256+col]; mode 1: half (b,head,row,32)
#define GPK 40   // smem pitch in halves
__global__ void __launch_bounds__(128) gemm_h(
    const float* __restrict__ Af, const __half* __restrict__ Ah,
    const float* __restrict__ W, const float* __restrict__ bias,
    void* __restrict__ Cv, int M, int rowsPerBatch, float scale, int mode)
{
    __shared__ __half As[64 * GPK];
    __shared__ __half Ws[64 * GPK];
    const int tid = threadIdx.x;
    const int lane = tid & 31;
    const int wid = tid >> 5;
    const int bm = blockIdx.x * 64;
    const int bn = blockIdx.y * 64;

    const int lrow = tid >> 1;          // 0..63
    const int lseg = (tid & 1) * 16;    // 0 or 16 (halves along k)

    float c[8][4];
#pragma unroll
    for (int j = 0; j < 8; j++) { c[j][0] = c[j][1] = c[j][2] = c[j][3] = 0.f; }

    const uint32_t AsB = smem_u32(As);
    const uint32_t WsB = smem_u32(Ws);

    for (int k0 = 0; k0 < 256; k0 += 32) {
        // stage A (64 x 32 halves)
        {
            int row = bm + lrow;
            uint4 u0, u1;
            if (Af) {
                float4 f0 = make_float4(0.f,0.f,0.f,0.f), f1 = f0, f2 = f0, f3 = f0;
                if (row < M) {
                    const float4* ap = (const float4*)&Af[(size_t)row * 256 + k0 + lseg];
                    f0 = ap[0]; f1 = ap[1]; f2 = ap[2]; f3 = ap[3];
                }
                u0.x = packh2(f0.x, f0.y); u0.y = packh2(f0.z, f0.w);
                u0.z = packh2(f1.x, f1.y); u0.w = packh2(f1.z, f1.w);
                u1.x = packh2(f2.x, f2.y); u1.y = packh2(f2.z, f2.w);
                u1.z = packh2(f3.x, f3.y); u1.w = packh2(f3.z, f3.w);
            } else {
                u0 = make_uint4(0,0,0,0); u1 = u0;
                if (row < M) {
                    const uint4* ap = (const uint4*)&Ah[(size_t)row * 256 + k0 + lseg];
                    u0 = ap[0]; u1 = ap[1];
                }
            }
            *(uint4*)&As[lrow * GPK + lseg]     = u0;
            *(uint4*)&As[lrow * GPK + lseg + 8] = u1;
        }
        // stage W (64 n-rows x 32 halves)
        {
            const float4* wp = (const float4*)&W[(size_t)(bn + lrow) * 256 + k0 + lseg];
            float4 f0 = wp[0], f1 = wp[1], f2 = wp[2], f3 = wp[3];
            uint4 u0, u1;
            u0.x = packh2(f0.x, f0.y); u0.y = packh2(f0.z, f0.w);
            u0.z = packh2(f1.x, f1.y); u0.w = packh2(f1.z, f1.w);
            u1.x = packh2(f2.x, f2.y); u1.y = packh2(f2.z, f2.w);
            u1.z = packh2(f3.x, f3.y); u1.w = packh2(f3.z, f3.w);
            *(uint4*)&Ws[lrow * GPK + lseg]     = u0;
            *(uint4*)&Ws[lrow * GPK + lseg + 8] = u1;
        }
        __syncthreads();

        // A fragments: rows wid*16..+15, k 0..31
        uint32_t a0[4], a1[4];
        {
            uint32_t aa = AsB + (uint32_t)((wid * 16 + (lane & 15)) * GPK + ((lane >> 4) * 8)) * 2;
            ldmx4(a0, aa);
            ldmx4(a1, aa + 32);
        }
#pragma unroll
        for (int j = 0; j < 8; j++) {
            int rr = j * 8 + (lane & 7);
            uint32_t addr = WsB + (uint32_t)(rr * GPK + ((lane >> 3) & 1) * 8) * 2;
            uint32_t b0[2], b1[2];
            ldmx2(b0, addr);
            ldmx2(b1, addr + 32);
            mma16816(c[j], a0, b0);
            mma16816(c[j], a1, b1);
        }
        __syncthreads();
    }

    // epilogue
    const int r0 = bm + wid * 16 + (lane >> 2);
    const int cb = 2 * (lane & 3);
    if (mode == 0) {
        float* C = (float*)Cv;
#pragma unroll
        for (int j = 0; j < 8; j++) {
            int col = bn + j * 8 + cb;
            float b0 = bias[col], b1 = bias[col + 1];
            if (r0 < M)     *(float2*)&C[(size_t)r0 * 256 + col]       = make_float2((c[j][0] + b0) * scale, (c[j][1] + b1) * scale);
            if (r0 + 8 < M) *(float2*)&C[(size_t)(r0 + 8) * 256 + col] = make_float2((c[j][2] + b0) * scale, (c[j][3] + b1) * scale);
        }
    } else {
        __half* C = (__half*)Cv;
        int ba = r0 / rowsPerBatch, ra = r0 - ba * rowsPerBatch;
        int bb2 = (r0 + 8) / rowsPerBatch, rb = (r0 + 8) - bb2 * rowsPerBatch;
#pragma unroll
        for (int j = 0; j < 8; j++) {
            int col = bn + j * 8 + cb;
            float b0 = bias[col], b1 = bias[col + 1];
            int head = col >> 5, d = col & 31;
            if (r0 < M) {
                uint32_t u = packh2((c[j][0] + b0) * scale, (c[j][1] + b1) * scale);
                *(uint32_t*)&C[((size_t)((ba * NH + head) * rowsPerBatch + ra)) * HD + d] = u;
            }
            if (r0 + 8 < M) {
                uint32_t u = packh2((c[j][2] + b0) * scale, (c[j][3] + b1) * scale);
                *(uint32_t*)&C[((size_t)((bb2 * NH + head) * rowsPerBatch + rb)) * HD + d] = u;
            }
        }
    }
}

// ---------------- RPE MLP: 4 queries per block ----------------
__global__ void __launch_bounds__(256) rpe_kernel4(const float* __restrict__ refpts,
                            const float* __restrict__ w1, const float* __restrict__ b1,
                            const float* __restrict__ w2, float* __restrict__ out, int axis)
{
    __shared__ float2 w1s[RPEH];
    __shared__ float  b1s[RPEH];
    __shared__ float  w2s[RPEH * NH];

    const int q0 = blockIdx.x * 4;
    const int b = blockIdx.y;
    const int tid = threadIdx.x;

    for (int i = tid; i < RPEH; i += 256) {
        w1s[i] = make_float2(w1[i * 2], w1[i * 2 + 1]);
        b1s[i] = b1[i];
    }
    for (int i = tid; i < RPEH * NH; i += 256) {
        int j = i >> 3, h = i & 7;
        w2s[i] = w2[h * RPEH + j];
    }

    const float* rp = refpts + ((size_t)b * QLEN + q0) * 4;
    float d0[4], d1[4];
    const int p  = tid >> 2;
    const int qr = tid & 3;
    const float px = (p + 0.5f) * 16.0f;
#pragma unroll
    for (int qq = 0; qq < 4; qq++) {
        float cc = rp[qq * 4 + axis];
        float ss = rp[qq * 4 + 2 + axis];
        d0[qq] = (cc - 0.5f * ss) * 1024.0f - px;
        d1[qq] = (cc + 0.5f * ss) * 1024.0f - px;
    }
    __syncthreads();

    float hQ[4][8];
#pragma unroll
    for (int qq = 0; qq < 4; qq++)
#pragma unroll
        for (int h = 0; h < 8; h++) hQ[qq][h] = 0.f;

#pragma unroll 2
    for (int i = 0; i < 128; i++) {
        int j = qr + i * 4;
        float2 w = w1s[j];
        float bb = b1s[j];
        const float4* wr = (const float4*)&w2s[j * 8];
        float4 wa = wr[0], wb = wr[1];
#pragma unroll
        for (int qq = 0; qq < 4; qq++) {
            float hv = fmaxf(w.x * d0[qq] + w.y * d1[qq] + bb, 0.0f);
            hQ[qq][0] += hv * wa.x; hQ[qq][1] += hv * wa.y;
            hQ[qq][2] += hv * wa.z; hQ[qq][3] += hv * wa.w;
            hQ[qq][4] += hv * wb.x; hQ[qq][5] += hv * wb.y;
            hQ[qq][6] += hv * wb.z; hQ[qq][7] += hv * wb.w;
        }
    }
#pragma unroll
    for (int m = 1; m <= 2; m <<= 1)
#pragma unroll
        for (int qq = 0; qq < 4; qq++)
#pragma unroll
            for (int h = 0; h < 8; h++)
                hQ[qq][h] += __shfl_xor_sync(0xffffffffu, hQ[qq][h], m);

    if (qr == 0) {
#pragma unroll
        for (int qq = 0; qq < 4; qq++)
#pragma unroll
            for (int h = 0; h < 8; h++)
                out[((size_t)(b * NH + h) * QLEN + q0 + qq) * GRD + p] = hQ[qq][h];
    }
}

// ---------------- HMMA flash attention ----------------
#define PK 40
#define PR 68
#define QS_OFF  0
#define KS_OFF  5120
#define VS_OFF  10240
#define RX_OFF  15360
#define RY_OFF  32768
#define MK_OFF  50176
#define ATTN_SMEM 66560

__global__ void __launch_bounds__(128) attn_mma(const int* __restrict__ mask)
{
    extern __shared__ char smem[];
    __half* Qs  = (__half*)(smem + QS_OFF);
    __half* Ks  = (__half*)(smem + KS_OFF);
    __half* Vs  = (__half*)(smem + VS_OFF);
    float*  rxs = (float*)(smem + RX_OFF);
    float*  rys = (float*)(smem + RY_OFF);
    float*  mks = (float*)(smem + MK_OFF);

    const int tid = threadIdx.x;
    const int lane = tid & 31;
    const int wid = tid >> 5;
    const int bh = blockIdx.y;
    const int b = bh >> 3;
    const int head = bh & 7;
    const int q0 = blockIdx.x * 64;

    const int* mb = mask + b * KVLEN;
    for (int i = tid; i < KVLEN; i += 128) mks[i] = -100.0f * (float)mb[i];

    {
        int row = tid >> 1, seg = tid & 1;
        int q = q0 + row;
        uint4 v0 = make_uint4(0, 0, 0, 0), v1 = make_uint4(0, 0, 0, 0);
        if (q < QLEN) {
            const uint4* qp = (const uint4*)(d_Qh + ((size_t)bh * QLEN + q) * HD + seg * 16);
            v0 = qp[0]; v1 = qp[1];
        }
        *(uint4*)(Qs + row * PK + seg * 16)     = v0;
        *(uint4*)(Qs + row * PK + seg * 16 + 8) = v1;
    }
    {
        int row = tid >> 1, sb = (tid & 1) * 32;
        int q = q0 + row;
        if (q < QLEN) {
            const float4* px = (const float4*)(d_rpex + ((size_t)bh * QLEN + q) * GRD + sb);
            const float4* py = (const float4*)(d_rpey + ((size_t)bh * QLEN + q) * GRD + sb);
#pragma unroll
            for (int u = 0; u < 8; u++) {
                *(float4*)(rxs + row * PR + sb + u * 4) = px[u];
                *(float4*)(rys + row * PR + sb + u * 4) = py[u];
            }
        } else {
            float4 z = make_float4(0.f, 0.f, 0.f, 0.f);
#pragma unroll
            for (int u = 0; u < 8; u++) {
                *(float4*)(rxs + row * PR + sb + u * 4) = z;
                *(float4*)(rys + row * PR + sb + u * 4) = z;
            }
        }
    }
    __syncthreads();

    uint32_t aQ[2][4];
    {
        uint32_t base = smem_u32(Qs);
        int m = wid * 16 + (lane & 15);
        uint32_t a0 = base + (uint32_t)(m * PK + ((lane >> 4) * 8)) * 2;
        ldmx4(aQ[0], a0);
        ldmx4(aQ[1], a0 + 32);
    }

    const uint32_t KsB = smem_u32(Ks);
    const uint32_t VsB = smem_u32(Vs);

    float oc[4][4];
#pragma unroll
    for (int i = 0; i < 4; i++)
#pragma unroll
        for (int j = 0; j < 4; j++) oc[i][j] = 0.f;
    float m_run0 = -1e30f, m_run1 = -1e30f, l_run0 = 0.f, l_run1 = 0.f;

    const __half* Kb = d_Kh + (size_t)bh * KVLEN * HD;
    const __half* Vb = d_Vh + (size_t)bh * KVLEN * HD;

    const int r0 = wid * 16 + (lane >> 2);
    const int cb = 2 * (lane & 3);

    for (int t = 0; t < 64; t++) {
        __syncthreads();
        {
            int row = tid >> 1, seg = tid & 1;
            const uint4* kp = (const uint4*)(Kb + (size_t)(t * 64 + row) * HD + seg * 16);
            const uint4* vp = (const uint4*)(Vb + (size_t)(t * 64 + row) * HD + seg * 16);
            uint4 k0 = kp[0], k1 = kp[1], v0 = vp[0], v1 = vp[1];
            *(uint4*)(Ks + row * PK + seg * 16)     = k0;
            *(uint4*)(Ks + row * PK + seg * 16 + 8) = k1;
            *(uint4*)(Vs + row * PK + seg * 16)     = v0;
            *(uint4*)(Vs + row * PK + seg * 16 + 8) = v1;
        }
        __syncthreads();

        float sc[8][4];
#pragma unroll
        for (int j = 0; j < 8; j++) {
            sc[j][0] = sc[j][1] = sc[j][2] = sc[j][3] = 0.f;
            int rr = j * 8 + (lane & 7);
            uint32_t addr = KsB + (uint32_t)(rr * PK + ((lane >> 3) & 1) * 8) * 2;
            uint32_t bk0[2], bk1[2];
            ldmx2(bk0, addr);
            ldmx2(bk1, addr + 32);
            mma16816(sc[j], aQ[0], bk0);
            mma16816(sc[j], aQ[1], bk1);
        }

        float ry0 = rys[r0 * PR + t];
        float ry1 = rys[(r0 + 8) * PR + t];
        float mx0 = -1e30f, mx1 = -1e30f;
#pragma unroll
        for (int j = 0; j < 8; j++) {
            int n = j * 8 + cb;
            float2 rxa = *(float2*)(rxs + r0 * PR + n);
            float2 rxb = *(float2*)(rxs + (r0 + 8) * PR + n);
            float2 mk  = *(float2*)(mks + t * 64 + n);
            sc[j][0] += rxa.x + ry0 + mk.x;
            sc[j][1] += rxa.y + ry0 + mk.y;
            sc[j][2] += rxb.x + ry1 + mk.x;
            sc[j][3] += rxb.y + ry1 + mk.y;
            mx0 = fmaxf(mx0, fmaxf(sc[j][0], sc[j][1]));
            mx1 = fmaxf(mx1, fmaxf(sc[j][2], sc[j][3]));
        }
        mx0 = fmaxf(mx0, __shfl_xor_sync(0xffffffffu, mx0, 1));
        mx0 = fmaxf(mx0, __shfl_xor_sync(0xffffffffu, mx0, 2));
        mx1 = fmaxf(mx1, __shfl_xor_sync(0xffffffffu, mx1, 1));
        mx1 = fmaxf(mx1, __shfl_xor_sync(0xffffffffu, mx1, 2));

        float mn0 = fmaxf(m_run0, mx0), mn1 = fmaxf(m_run1, mx1);
        float f0 = __expf(m_run0 - mn0), f1 = __expf(m_run1 - mn1);
        m_run0 = mn0; m_run1 = mn1;

        float la0 = 0.f, la1 = 0.f;
        uint32_t pa[4][4];
#pragma unroll
        for (int j = 0; j < 8; j++) {
            float p0 = __expf(sc[j][0] - mn0);
            float p1 = __expf(sc[j][1] - mn0);
            float p2 = __expf(sc[j][2] - mn1);
            float p3 = __expf(sc[j][3] - mn1);
            la0 += p0 + p1; la1 += p2 + p3;
            int kt = j >> 1, hi = j & 1;
            pa[kt][2 * hi]     = packh2(p0, p1);
            pa[kt][2 * hi + 1] = packh2(p2, p3);
        }
        la0 += __shfl_xor_sync(0xffffffffu, la0, 1);
        la0 += __shfl_xor_sync(0xffffffffu, la0, 2);
        la1 += __shfl_xor_sync(0xffffffffu, la1, 1);
        la1 += __shfl_xor_sync(0xffffffffu, la1, 2);
        l_run0 = l_run0 * f0 + la0;
        l_run1 = l_run1 * f1 + la1;

#pragma unroll
        for (int no = 0; no < 4; no++) {
            oc[no][0] *= f0; oc[no][1] *= f0;
            oc[no][2] *= f1; oc[no][3] *= f1;
        }

#pragma unroll
        for (int kt = 0; kt < 4; kt++) {
            uint32_t addr = VsB + (uint32_t)((kt * 16 + (lane & 15)) * PK) * 2;
#pragma unroll
            for (int no = 0; no < 4; no++) {
                uint32_t bv[2];
                ldmx2t(bv, addr + (uint32_t)(no * 8) * 2);
                mma16816(oc[no], pa[kt], bv);
            }
        }
    }

    {
        float inv0 = 1.0f / l_run0;
        float inv1 = 1.0f / l_run1;
        int qa = q0 + r0, qb = qa + 8;
#pragma unroll
        for (int no = 0; no < 4; no++) {
            int col = head * HD + no * 8 + cb;
            if (qa < QLEN) {
                uint32_t u = packh2(oc[no][0] * inv0, oc[no][1] * inv0);
                *(uint32_t*)&d_ctxh[((size_t)b * QLEN + qa) * DIMV + col] = u;
            }
            if (qb < QLEN) {
                uint32_t u = packh2(oc[no][2] * inv1, oc[no][3] * inv1);
                *(uint32_t*)&d_ctxh[((size_t)b * QLEN + qb) * DIMV + col] = u;
            }
        }
    }
}

// ---------------- launch ----------------
extern "C" void kernel_launch(void* const* d_in, const int* in_sizes, int n_in,
                              void* d_out, int out_size)
{
    const float* hidden = (const float*)d_in[0];
    const float* refpts = (const float*)d_in[1];
    const float* kvst   = (const float*)d_in[2];
    const int*   amask  = (const int*)d_in[4];
    const float* m1w1 = (const float*)d_in[5];
    const float* m1b1 = (const float*)d_in[6];
    const float* m1w2 = (const float*)d_in[7];
    const float* m2w1 = (const float*)d_in[8];
    const float* m2b1 = (const float*)d_in[9];
    const float* m2w2 = (const float*)d_in[10];
    const float* qw = (const float*)d_in[11];
    const float* qb = (const float*)d_in[12];
    const float* kw = (const float*)d_in[13];
    const float* kb = (const float*)d_in[14];
    const float* vw = (const float*)d_in[15];
    const float* vb = (const float*)d_in[16];
    const float* ow = (const float*)d_in[17];
    const float* ob = (const float*)d_in[18];
    float* out = (float*)d_out;

    void *pQ, *pK, *pV, *pRX, *pRY, *pCTX;
    cudaGetSymbolAddress(&pQ,  d_Qh);
    cudaGetSymbolAddress(&pK,  d_Kh);
    cudaGetSymbolAddress(&pV,  d_Vh);
    cudaGetSymbolAddress(&pRX, d_rpex);
    cudaGetSymbolAddress(&pRY, d_rpey);
    cudaGetSymbolAddress(&pCTX, d_ctxh);

    static int smem_set = 0;
    if (!smem_set) {
        cudaFuncSetAttribute(attn_mma, cudaFuncAttributeMaxDynamicSharedMemorySize, ATTN_SMEM);
        smem_set = 1;
    }

    const float qscale = 0.17677669529663687f;  // 1/sqrt(32)

    gemm_h<<<dim3(128, 4), 128>>>(kvst, nullptr, kw, kb, pK, B_ * KVLEN, KVLEN, 1.0f, 1);
    gemm_h<<<dim3(128, 4), 128>>>(kvst, nullptr, vw, vb, pV, B_ * KVLEN, KVLEN, 1.0f, 1);
    gemm_h<<<dim3(29, 4),  128>>>(hidden, nullptr, qw, qb, pQ, B_ * QLEN, QLEN, qscale, 1);
    rpe_kernel4<<<dim3(QLEN / 4, B_), 256>>>(refpts, m1w1, m1b1, m1w2, (float*)pRX, 0);
    rpe_kernel4<<<dim3(QLEN / 4, B_), 256>>>(refpts, m2w1, m2b1, m2w2, (float*)pRY, 1);
    attn_mma<<<dim3((QLEN + 63) / 64, B_ * NH), 128, ATTN_SMEM>>>(amask);
    gemm_h<<<dim3(29, 4),  128>>>(nullptr, (const __half*)pCTX, ow, ob, out, B_ * QLEN, QLEN, 1.0f, 0);
}